// round 11
// baseline (speedup 1.0000x reference)
#include <cuda_runtime.h>
#include <cstdint>

#define B_DIM 2048
#define K_DIM 256
#define U_DIM 512

typedef unsigned long long u64t;

// ---- packed f32x2 helpers (sm_103a) ----
__device__ __forceinline__ u64t f2_fma(u64t a, u64t b, u64t c) {
    u64t d;
    asm("fma.rn.f32x2 %0, %1, %2, %3;" : "=l"(d) : "l"(a), "l"(b), "l"(c));
    return d;
}
__device__ __forceinline__ u64t f2_mul(u64t a, u64t b) {
    u64t d;
    asm("mul.rn.f32x2 %0, %1, %2;" : "=l"(d) : "l"(a), "l"(b));
    return d;
}
__device__ __forceinline__ u64t f2_pack(float a, float b) {
    u64t d;
    asm("mov.b64 %0, {%1, %2};" : "=l"(d) : "f"(a), "f"(b));
    return d;
}
__device__ __forceinline__ float2 f2_unpack(u64t v) {
    float2 r;
    asm("mov.b64 {%0, %1}, %2;" : "=f"(r.x), "=f"(r.y) : "l"(v));
    return r;
}

// No shared memory, no barriers. CTA: 256 threads, tile 64b x 64u.
// Thread tile: 4 b-rows x 4 u-cols. f32x2 lanes are packed over K
// (even-k/odd-k partial products, multiplied together in the epilogue),
// so each float4 x-load natively yields two packed operands.
__global__ void pew_kernel(const float* __restrict__ x,
                           const float* __restrict__ w,
                           float* __restrict__ out) {
    const int tid = threadIdx.x;
    const int tx  = tid & 15;                   // u: 16 threads x 4 cols
    const int ty  = tid >> 4;                   // b: 16 threads x 4 rows
    const int u0  = blockIdx.x * 64 + tx * 4;
    const int b0  = blockIdx.y * 64 + ty * 4;

    const u64t ONE2 = 0x3F8000003F800000ULL;    // { 1.0f,  1.0f}
    const u64t M1   = 0xBF800000BF800000ULL;    // {-1.0f, -1.0f}

    u64t acc[4][4];
#pragma unroll
    for (int r = 0; r < 4; r++)
#pragma unroll
        for (int c = 0; c < 4; c++) acc[r][c] = ONE2;

    const float* xbase = x + b0 * K_DIM;
    const float* wbase = w + u0;

#pragma unroll 1
    for (int kc = 0; kc < K_DIM / 4; kc++) {
        const int k4 = kc * 4;

        // 4 w-rows (k4..k4+3): warp covers 64 u = 256B contiguous per row.
        float4 wr[4];
#pragma unroll
        for (int p = 0; p < 4; p++)
            wr[p] = *(const float4*)(wbase + (k4 + p) * U_DIM);

        // 4 x-rows, 4 consecutive k each (16B): 8 distinct broadcast
        // addresses per warp.
        float4 xr[4];
#pragma unroll
        for (int r = 0; r < 4; r++)
            xr[r] = *(const float4*)(xbase + r * K_DIM + k4);

        // two k-pair halves: h=0 -> (k4,k4+1), h=1 -> (k4+2,k4+3)
#pragma unroll
        for (int h = 0; h < 2; h++) {
            u64t wpk[4], wc[4];
#pragma unroll
            for (int c = 0; c < 4; c++) {
                const float wa = ((const float*)&wr[2 * h])[c];
                const float wb = ((const float*)&wr[2 * h + 1])[c];
                wpk[c] = f2_pack(wa, wb);               // (w[k], w[k+1])
                wc[c]  = f2_fma(wpk[c], M1, ONE2);      // 1 - w
            }
#pragma unroll
            for (int r = 0; r < 4; r++) {
                const ulonglong2 xq = *(const ulonglong2*)&xr[r];
                const u64t xv = h ? xq.y : xq.x;        // native (x[k], x[k+1])
#pragma unroll
                for (int c = 0; c < 4; c++) {
                    // term = x*w + (1-w)
                    const u64t t = f2_fma(xv, wpk[c], wc[c]);
                    acc[r][c] = f2_mul(acc[r][c], t);
                }
            }
        }
    }

    // epilogue: combine even-k/odd-k halves, coalesced STG.128
#pragma unroll
    for (int r = 0; r < 4; r++) {
        const float2 a0 = f2_unpack(acc[r][0]);
        const float2 a1 = f2_unpack(acc[r][1]);
        const float2 a2 = f2_unpack(acc[r][2]);
        const float2 a3 = f2_unpack(acc[r][3]);
        float4 o;
        o.x = a0.x * a0.y;
        o.y = a1.x * a1.y;
        o.z = a2.x * a2.y;
        o.w = a3.x * a3.y;
        *(float4*)(out + (b0 + r) * U_DIM + u0) = o;
    }
}

extern "C" void kernel_launch(void* const* d_in, const int* in_sizes, int n_in,
                              void* d_out, int out_size) {
    const float* x = (const float*)d_in[0];   // [2048, 256]
    const float* w = (const float*)d_in[1];   // [256 * 512], k-major, u contiguous
    float* out = (float*)d_out;               // [2048, 512]

    dim3 grid(U_DIM / 64, B_DIM / 64);        // (8, 32) = 256 blocks
    pew_kernel<<<grid, 256>>>(x, w, out);
}

// round 12
// speedup vs baseline: 1.4226x; 1.4226x over previous
#include <cuda_runtime.h>
#include <cstdint>

#define B_DIM 2048
#define K_DIM 256
#define U_DIM 512

#define BM 64
#define BN 64
#define BK 16                 // k per tile; 8 k-pairs inner iterations
#define NK2 (BK / 2)          // 8
#define NTILES (K_DIM / BK)   // 16
#define SX_STRIDE (BM + 2)    // 66 u64 = 528B row (16B-aligned)

typedef unsigned long long u64t;

// ---- packed f32x2 helpers (sm_103a) ----
__device__ __forceinline__ u64t f2_fma(u64t a, u64t b, u64t c) {
    u64t d;
    asm("fma.rn.f32x2 %0, %1, %2, %3;" : "=l"(d) : "l"(a), "l"(b), "l"(c));
    return d;
}
__device__ __forceinline__ u64t f2_mul(u64t a, u64t b) {
    u64t d;
    asm("mul.rn.f32x2 %0, %1, %2;" : "=l"(d) : "l"(a), "l"(b));
    return d;
}
__device__ __forceinline__ u64t f2_pack(float a, float b) {
    u64t d;
    asm("mov.b64 %0, {%1, %2};" : "=l"(d) : "f"(a), "f"(b));
    return d;
}
__device__ __forceinline__ float2 f2_unpack(u64t v) {
    float2 r;
    asm("mov.b64 {%0, %1}, %2;" : "=f"(r.x), "=f"(r.y) : "l"(v));
    return r;
}

// f32x2 lanes packed over K (even-k / odd-k partial products; halves
// multiplied in the epilogue). Both smem operands are stored PRE-PAIRED:
//   sx2[k2][b] = (1-x[b][2k2], 1-x[b][2k2+1])
//   sw2[k2][u] = (-w[2k2][u], -w[2k2+1][u])
// so the hot loop is LDS.128 -> FFMA2 -> FMUL2 with zero MOV packs.
__global__ __launch_bounds__(256, 2)
void pew_kernel(const float* __restrict__ x,
                const float* __restrict__ w,
                float* __restrict__ out) {
    __shared__ __align__(16) u64t sx2[2][NK2][SX_STRIDE];
    __shared__ __align__(16) u64t sw2[2][NK2][BN];

    const int tid = threadIdx.x;
    const int tx  = tid & 15;          // u: 16 threads x 4 cols
    const int ty  = tid >> 4;          // b: 16 threads x 4 rows
    const int ub  = blockIdx.x * BN;
    const int bb  = blockIdx.y * BM;

    // staging coordinates
    const int xb0 = tid >> 2;          // 0..63 : x row within tile
    const int xk2 = (tid & 3) * 2;     // k2 base (pairs) for x staging
    const int wk2 = tid >> 5;          // 0..7  : k2 row for w staging
    const int wl  = tid & 31;          // covers u-pairs 2*wl, 2*wl+1

    const u64t ONE2 = 0x3F8000003F800000ULL; // {1.0f, 1.0f}

    u64t acc[4][4];                    // [b][u], lanes = (even-k, odd-k)
#pragma unroll
    for (int r = 0; r < 4; r++)
#pragma unroll
        for (int c = 0; c < 4; c++) acc[r][c] = ONE2;

    // ---- stage tile 0 ----
    float4 rx  = *(const float4*)(x + (bb + xb0) * K_DIM + (tid & 3) * 4);
    float2 rwa = *(const float2*)(w + (2 * wk2 + 0) * U_DIM + ub + wl * 2);
    float2 rwb = *(const float2*)(w + (2 * wk2 + 1) * U_DIM + ub + wl * 2);

    sx2[0][xk2 + 0][xb0] = f2_pack(1.0f - rx.x, 1.0f - rx.y);
    sx2[0][xk2 + 1][xb0] = f2_pack(1.0f - rx.z, 1.0f - rx.w);
    {
        ulonglong2 q;
        q.x = f2_pack(-rwa.x, -rwb.x);
        q.y = f2_pack(-rwa.y, -rwb.y);
        *(ulonglong2*)&sw2[0][wk2][wl * 2] = q;
    }
    __syncthreads();

#pragma unroll 1
    for (int t = 0; t < NTILES; t++) {
        const int cur = t & 1;

        // prefetch next tile (overlaps with compute below)
        if (t + 1 < NTILES) {
            const int k0 = (t + 1) * BK;
            rx  = *(const float4*)(x + (bb + xb0) * K_DIM + k0 + (tid & 3) * 4);
            rwa = *(const float2*)(w + (k0 + 2 * wk2 + 0) * U_DIM + ub + wl * 2);
            rwb = *(const float2*)(w + (k0 + 2 * wk2 + 1) * U_DIM + ub + wl * 2);
        }

        // ---- compute on buffer `cur`: 8 k-pairs ----
#pragma unroll
        for (int k2 = 0; k2 < NK2; k2++) {
            const ulonglong2 y01 = *(const ulonglong2*)&sx2[cur][k2][ty * 4];
            const ulonglong2 y23 = *(const ulonglong2*)&sx2[cur][k2][ty * 4 + 2];
            const ulonglong2 w01 = *(const ulonglong2*)&sw2[cur][k2][tx * 4];
            const ulonglong2 w23 = *(const ulonglong2*)&sw2[cur][k2][tx * 4 + 2];

            const u64t yv[4] = {y01.x, y01.y, y23.x, y23.y};
            const u64t wv[4] = {w01.x, w01.y, w23.x, w23.y};
#pragma unroll
            for (int r = 0; r < 4; r++)
#pragma unroll
                for (int c = 0; c < 4; c++) {
                    // per lane: term = 1 + (-w)*(1-x) = x*w + (1-w)
                    const u64t tt = f2_fma(wv[c], yv[r], ONE2);
                    acc[r][c] = f2_mul(acc[r][c], tt);
                }
        }

        // ---- store prefetched tile into the other buffer ----
        if (t + 1 < NTILES) {
            const int nb = cur ^ 1;
            sx2[nb][xk2 + 0][xb0] = f2_pack(1.0f - rx.x, 1.0f - rx.y);
            sx2[nb][xk2 + 1][xb0] = f2_pack(1.0f - rx.z, 1.0f - rx.w);
            ulonglong2 q;
            q.x = f2_pack(-rwa.x, -rwb.x);
            q.y = f2_pack(-rwa.y, -rwb.y);
            *(ulonglong2*)&sw2[nb][wk2][wl * 2] = q;
            __syncthreads();
        }
    }

    // ---- epilogue: multiply even/odd halves, coalesced STG.128 ----
    const int ob = bb + ty * 4;
    const int ou = ub + tx * 4;
#pragma unroll
    for (int r = 0; r < 4; r++) {
        const float2 a0 = f2_unpack(acc[r][0]);
        const float2 a1 = f2_unpack(acc[r][1]);
        const float2 a2 = f2_unpack(acc[r][2]);
        const float2 a3 = f2_unpack(acc[r][3]);
        float4 o;
        o.x = a0.x * a0.y;
        o.y = a1.x * a1.y;
        o.z = a2.x * a2.y;
        o.w = a3.x * a3.y;
        *(float4*)(out + (ob + r) * U_DIM + ou) = o;
    }
}

extern "C" void kernel_launch(void* const* d_in, const int* in_sizes, int n_in,
                              void* d_out, int out_size) {
    const float* x = (const float*)d_in[0];   // [2048, 256]
    const float* w = (const float*)d_in[1];   // [256 * 512], k-major, u contiguous
    float* out = (float*)d_out;               // [2048, 512]

    dim3 grid(U_DIM / BN, B_DIM / BM);        // (8, 32) = 256 blocks
    pew_kernel<<<grid, 256>>>(x, w, out);
}

// round 14
// speedup vs baseline: 1.6809x; 1.1816x over previous
#include <cuda_runtime.h>
#include <cstdint>

#define B_DIM 2048
#define K_DIM 256
#define U_DIM 512

#define BM 64
#define BN 64
#define BK 16
#define NTILES (K_DIM / BK)   // 16
#define SY_STRIDE (BM + 4)    // 68 floats = 272B row (16B-aligned)

typedef unsigned long long u64t;

// ---- packed f32x2 helpers (sm_103a) ----
__device__ __forceinline__ u64t f2_fma(u64t a, u64t b, u64t c) {
    u64t d;
    asm("fma.rn.f32x2 %0, %1, %2, %3;" : "=l"(d) : "l"(a), "l"(b), "l"(c));
    return d;
}
__device__ __forceinline__ u64t f2_mul(u64t a, u64t b) {
    u64t d;
    asm("mul.rn.f32x2 %0, %1, %2;" : "=l"(d) : "l"(a), "l"(b));
    return d;
}
__device__ __forceinline__ u64t f2_pack(float a, float b) {
    u64t d;
    asm("mov.b64 %0, {%1, %2};" : "=l"(d) : "f"(a), "f"(b));
    return d;
}
__device__ __forceinline__ float2 f2_unpack(u64t v) {
    float2 r;
    asm("mov.b64 {%0, %1}, %2;" : "=f"(r.x), "=f"(r.y) : "l"(v));
    return r;
}

// R2's wavefront-optimal per-warp structure (8b x 4u thread tile, broadcast-y,
// contiguous scalar-w) in 128-thread CTAs: 4 independent CTAs/SM so barrier
// domains decorrelate and LDS latency is hidden.
__global__ __launch_bounds__(128, 4)
void pew_kernel(const float* __restrict__ x,
                const float* __restrict__ w,
                float* __restrict__ out) {
    // sY: y = 1 - x transposed to [k][b] (b contiguous); sW: -w in [k][u].
    __shared__ __align__(16) float sY[2][BK][SY_STRIDE];
    __shared__ __align__(16) float sW[2][BK][BN];

    const int tid = threadIdx.x;
    const int tx  = tid & 15;          // u: 16 threads x 4 cols
    const int ty  = tid >> 4;          // b: 8 threads x 8 rows
    const int ub  = blockIdx.x * BN;
    const int bb  = blockIdx.y * BM;

    // staging coordinates (each thread covers 2 x-slots and 2 w-slots)
    const int xb0 = tid >> 2;          // 0..31 ; second slot at +32
    const int xkq = (tid & 3) * 4;     // k-quad within tile
    const int wu  = (tid & 15) * 4;    // u offset for w float4
    const int wk  = tid >> 4;          // 0..7 ; second slot at +8

    const u64t ONE2 = 0x3F8000003F800000ULL; // {1.0f, 1.0f}

    u64t acc[4][4];                    // [b-pair][u], packed over b
#pragma unroll
    for (int i = 0; i < 4; i++)
#pragma unroll
        for (int j = 0; j < 4; j++) acc[i][j] = ONE2;

    // ---- stage tile 0 ----
    float4 rx0 = *(const float4*)(x + (bb + xb0) * K_DIM + xkq);
    float4 rx1 = *(const float4*)(x + (bb + xb0 + 32) * K_DIM + xkq);
    float4 rw0 = *(const float4*)(w + wk * U_DIM + ub + wu);
    float4 rw1 = *(const float4*)(w + (wk + 8) * U_DIM + ub + wu);

    sY[0][xkq + 0][xb0] = 1.0f - rx0.x;
    sY[0][xkq + 1][xb0] = 1.0f - rx0.y;
    sY[0][xkq + 2][xb0] = 1.0f - rx0.z;
    sY[0][xkq + 3][xb0] = 1.0f - rx0.w;
    sY[0][xkq + 0][xb0 + 32] = 1.0f - rx1.x;
    sY[0][xkq + 1][xb0 + 32] = 1.0f - rx1.y;
    sY[0][xkq + 2][xb0 + 32] = 1.0f - rx1.z;
    sY[0][xkq + 3][xb0 + 32] = 1.0f - rx1.w;
    *(float4*)&sW[0][wk][wu]     = make_float4(-rw0.x, -rw0.y, -rw0.z, -rw0.w);
    *(float4*)&sW[0][wk + 8][wu] = make_float4(-rw1.x, -rw1.y, -rw1.z, -rw1.w);
    __syncthreads();

#pragma unroll 1
    for (int t = 0; t < NTILES; t++) {
        const int cur = t & 1;

        // prefetch next tile (overlaps with compute below)
        if (t + 1 < NTILES) {
            const int k0 = (t + 1) * BK;
            rx0 = *(const float4*)(x + (bb + xb0) * K_DIM + k0 + xkq);
            rx1 = *(const float4*)(x + (bb + xb0 + 32) * K_DIM + k0 + xkq);
            rw0 = *(const float4*)(w + (k0 + wk) * U_DIM + ub + wu);
            rw1 = *(const float4*)(w + (k0 + wk + 8) * U_DIM + ub + wu);
        }

        // ---- compute on buffer `cur` ----
#pragma unroll
        for (int k = 0; k < BK; k++) {
            // 8 consecutive y values (b-contiguous): 2 broadcast LDS.128
            // (2 distinct addrs per warp each -> 1 wavefront each)
            const ulonglong2 ya = *(const ulonglong2*)&sY[cur][k][ty * 8];
            const ulonglong2 yb = *(const ulonglong2*)&sY[cur][k][ty * 8 + 4];
            // 4 w scalars: contiguous 256B per warp -> 2 wavefronts
            const float4 wv = *(const float4*)&sW[cur][k][tx * 4];

            u64t wp[4];
            wp[0] = f2_pack(wv.x, wv.x);
            wp[1] = f2_pack(wv.y, wv.y);
            wp[2] = f2_pack(wv.z, wv.z);
            wp[3] = f2_pack(wv.w, wv.w);

            const u64t yv[4] = {ya.x, ya.y, yb.x, yb.y};
#pragma unroll
            for (int i = 0; i < 4; i++)
#pragma unroll
                for (int j = 0; j < 4; j++) {
                    // term = 1 + (-w)*(1-x);  acc *= term  via
                    //   p = (-w)*(1-x);  acc = p*acc + acc
                    const u64t p = f2_mul(wp[j], yv[i]);
                    acc[i][j] = f2_fma(p, acc[i][j], acc[i][j]);
                }
        }

        // ---- store prefetched tile into the other buffer ----
        if (t + 1 < NTILES) {
            const int nb = cur ^ 1;
            sY[nb][xkq + 0][xb0] = 1.0f - rx0.x;
            sY[nb][xkq + 1][xb0] = 1.0f - rx0.y;
            sY[nb][xkq + 2][xb0] = 1.0f - rx0.z;
            sY[nb][xkq + 3][xb0] = 1.0f - rx0.w;
            sY[nb][xkq + 0][xb0 + 32] = 1.0f - rx1.x;
            sY[nb][xkq + 1][xb0 + 32] = 1.0f - rx1.y;
            sY[nb][xkq + 2][xb0 + 32] = 1.0f - rx1.z;
            sY[nb][xkq + 3][xb0 + 32] = 1.0f - rx1.w;
            *(float4*)&sW[nb][wk][wu]     = make_float4(-rw0.x, -rw0.y, -rw0.z, -rw0.w);
            *(float4*)&sW[nb][wk + 8][wu] = make_float4(-rw1.x, -rw1.y, -rw1.z, -rw1.w);
            __syncthreads();
        }
    }

    // ---- epilogue: unpack b-pairs, vectorized STG.128 ----
    const int ob = bb + ty * 8;
    const int ou = ub + tx * 4;
#pragma unroll
    for (int i2 = 0; i2 < 4; i2++) {
        const float2 c0 = f2_unpack(acc[i2][0]);
        const float2 c1 = f2_unpack(acc[i2][1]);
        const float2 c2 = f2_unpack(acc[i2][2]);
        const float2 c3 = f2_unpack(acc[i2][3]);
        float4 vlo = make_float4(c0.x, c1.x, c2.x, c3.x);
        float4 vhi = make_float4(c0.y, c1.y, c2.y, c3.y);
        *(float4*)(out + (ob + i2 * 2 + 0) * U_DIM + ou) = vlo;
        *(float4*)(out + (ob + i2 * 2 + 1) * U_DIM + ou) = vhi;
    }
}

extern "C" void kernel_launch(void* const* d_in, const int* in_sizes, int n_in,
                              void* d_out, int out_size) {
    const float* x = (const float*)d_in[0];   // [2048, 256]
    const float* w = (const float*)d_in[1];   // [256 * 512], k-major, u contiguous
    float* out = (float*)d_out;               // [2048, 512]

    dim3 grid(U_DIM / BN, B_DIM / BM);        // (8, 32) = 256 blocks
    pew_kernel<<<grid, 128>>>(x, w, out);
}